// round 6
// baseline (speedup 1.0000x reference)
#include <cuda_runtime.h>
#include <cuda_bf16.h>
#include <math.h>
#include <stdint.h>

#define BB 8
#define CC 512
#define HH 32
#define WW 32
#define LL 1024   // H*W
#define NHD 8
#define HD 64
#define WHALF 16  // WINDOW/2

// ---------------- scratch (static device globals; no runtime allocation) ----
__device__ float g_xwalze[BB*CC*HH*WW];          // (B,C,H,W) post-walze
__device__ __nv_bfloat16 g_comb[BB*LL*2*CC];     // (B*L, 2C): [before | after]
__device__ float g_mask[BB*LL];                  // soft mask
__device__ float g_qkv[BB*LL*3*CC];              // (B*L, 3C)
__device__ __nv_bfloat16 g_ctx[BB*LL*CC];        // attention context (bf16)
__device__ __nv_bfloat16 g_ipw[3*CC*CC];         // bf16 in_proj_w
__device__ __nv_bfloat16 g_opw[CC*CC];           // bf16 out_proj_w
__device__ __nv_bfloat16 g_w1[128*2*CC];         // bf16 det_w1

__device__ __forceinline__ float gelu_exact(float v) {
    return 0.5f * v * (1.0f + erff(v * 0.70710678118654752440f));
}
__device__ __forceinline__ uint32_t smem_u32(const void* p) {
    uint32_t a;
    asm("{ .reg .u64 t; cvta.to.shared.u64 t, %1; cvt.u32.u64 %0, t; }"
        : "=r"(a) : "l"(p));
    return a;
}
__device__ __forceinline__ void cp16(uint32_t dst, const void* src) {
    asm volatile("cp.async.cg.shared.global [%0], [%1], 16;" :: "r"(dst), "l"(src));
}
__device__ __forceinline__ void ldmx4(uint32_t addr, uint32_t& r0, uint32_t& r1,
                                      uint32_t& r2, uint32_t& r3) {
    asm volatile("ldmatrix.sync.aligned.m8n8.x4.shared.b16 {%0,%1,%2,%3}, [%4];"
                 : "=r"(r0), "=r"(r1), "=r"(r2), "=r"(r3) : "r"(addr));
}
__device__ __forceinline__ void mma16(float* c, uint32_t a0, uint32_t a1,
                                      uint32_t a2, uint32_t a3,
                                      uint32_t b0, uint32_t b1) {
    asm volatile("mma.sync.aligned.m16n8k16.row.col.f32.bf16.bf16.f32 "
                 "{%0,%1,%2,%3}, {%4,%5,%6,%7}, {%8,%9}, {%0,%1,%2,%3};"
                 : "+f"(c[0]), "+f"(c[1]), "+f"(c[2]), "+f"(c[3])
                 : "r"(a0), "r"(a1), "r"(a2), "r"(a3), "r"(b0), "r"(b1));
}

// ====== bf16 mma.sync GEMM: C(M,N) = A(M,K) * B(N,K)^T + bias ===============
// CTA tile (MT*32) x 128, 8 warps (2 m x 4 n). K-chunk 64 bf16 (128B rows),
// double-buffered cp.async, xor-swizzled smem.
// EPI: 0 = plain store, 2 = detector head (gelu . w2 -> sigmoid -> mask),
//      3 = fused combine (out = xwalze + mask * (v + bias), transposed store).
template<int EPI, int MT>
__global__ void __launch_bounds__(256, 2)
mma_gemm(const __nv_bfloat16* __restrict__ A, int lda,
         const __nv_bfloat16* __restrict__ Bm, int ldb,
         const float* __restrict__ bias,
         float* __restrict__ Cm, int ldc, int K,
         const float* __restrict__ aux1,   // EPI2: w2      EPI3: mask
         const float* __restrict__ aux2)   // EPI2: b2      EPI3: xwalze
{
    constexpr int TM = MT * 32;
    constexpr int ABYTES = TM * 128;
    constexpr int BUFB = ABYTES + 16384;
    extern __shared__ char smem[];
    const uint32_t sb = smem_u32(smem);
    const int tid = threadIdx.x, lane = tid & 31, wid = tid >> 5;
    const int bm = blockIdx.y * TM, bn = blockIdx.x * 128;
    const int wm0 = (wid & 1) * (TM / 2), wn0 = (wid >> 1) * 32;

    const int ld_row = tid >> 3;
    const uint32_t st_off =
        (uint32_t)(ld_row * 128 + (((tid & 7) * 16) ^ ((ld_row & 7) << 4)));
    const __nv_bfloat16* Agb = A  + (size_t)(bm + ld_row) * lda + (tid & 7) * 8;
    const __nv_bfloat16* Bgb = Bm + (size_t)(bn + ld_row) * ldb + (tid & 7) * 8;

    auto load_tile = [&](int buf, int ch) {
        uint32_t da = sb + buf * BUFB + st_off;
        uint32_t db = da + ABYTES;
        const __nv_bfloat16* sa  = Agb + ch * 64;
        const __nv_bfloat16* sbp = Bgb + ch * 64;
#pragma unroll
        for (int p = 0; p < MT; p++)
            cp16(da + p * 4096, sa + (size_t)p * 32 * lda);
#pragma unroll
        for (int p = 0; p < 4; p++)
            cp16(db + p * 4096, sbp + (size_t)p * 32 * ldb);
        asm volatile("cp.async.commit_group;" ::: "memory");
    };

    const int arow  = wm0 + (lane & 15);
    const uint32_t akb = ((uint32_t)(lane >> 4)) << 4;
    const uint32_t aswz = (uint32_t)((arow & 7) << 4);
    const uint32_t a_rowbase = (uint32_t)(arow * 128);
    const int brow  = wn0 + ((lane >> 4) << 3) + (lane & 7);
    const uint32_t bkb = (uint32_t)(((lane >> 3) & 1) << 4);
    const uint32_t bswz = (uint32_t)((brow & 7) << 4);
    const uint32_t b_rowbase = (uint32_t)(ABYTES + brow * 128);

    float c[MT][4][4];
#pragma unroll
    for (int i = 0; i < MT; i++)
#pragma unroll
        for (int j = 0; j < 4; j++)
#pragma unroll
            for (int k = 0; k < 4; k++) c[i][j][k] = 0.0f;

    const int nch = K >> 6;
    load_tile(0, 0);
    load_tile(1, 1);

    for (int ch = 0; ch < nch; ch++) {
        const int buf = ch & 1;
        if (ch + 1 < nch) asm volatile("cp.async.wait_group 1;" ::: "memory");
        else              asm volatile("cp.async.wait_group 0;" ::: "memory");
        __syncthreads();

        const uint32_t base = sb + buf * BUFB;
#pragma unroll
        for (int ks = 0; ks < 4; ks++) {
            const uint32_t kso = (uint32_t)(ks * 32);
            uint32_t a[MT][4];
#pragma unroll
            for (int mt = 0; mt < MT; mt++)
                ldmx4(base + a_rowbase + (uint32_t)(mt * 2048) + ((kso + akb) ^ aswz),
                      a[mt][0], a[mt][1], a[mt][2], a[mt][3]);
            uint32_t b[4][2];
#pragma unroll
            for (int nt2 = 0; nt2 < 2; nt2++)
                ldmx4(base + b_rowbase + (uint32_t)(nt2 * 2048) + ((kso + bkb) ^ bswz),
                      b[nt2*2][0], b[nt2*2][1], b[nt2*2+1][0], b[nt2*2+1][1]);
#pragma unroll
            for (int mt = 0; mt < MT; mt++)
#pragma unroll
                for (int nt = 0; nt < 4; nt++)
                    mma16(c[mt][nt], a[mt][0], a[mt][1], a[mt][2], a[mt][3],
                          b[nt][0], b[nt][1]);
        }
        __syncthreads();
        if (ch + 2 < nch) load_tile(buf, ch + 2);
    }

    if (EPI == 2) {
        // detector head: logit[r] = sum_col gelu(v+b1)[r,col] * w2[col]
        float* red = (float*)smem;
        __syncthreads();
        if (tid < TM) red[tid] = 0.0f;
        __syncthreads();
#pragma unroll
        for (int mt = 0; mt < MT; mt++) {
            float pA = 0.0f, pB = 0.0f;
#pragma unroll
            for (int nt = 0; nt < 4; nt++) {
                int col = bn + wn0 + nt * 8 + (lane & 3) * 2;
                float2 bs = *(const float2*)(bias + col);
                float w0 = aux1[col], w1 = aux1[col + 1];
                pA += gelu_exact(c[mt][nt][0] + bs.x) * w0
                    + gelu_exact(c[mt][nt][1] + bs.y) * w1;
                pB += gelu_exact(c[mt][nt][2] + bs.x) * w0
                    + gelu_exact(c[mt][nt][3] + bs.y) * w1;
            }
            pA += __shfl_xor_sync(0xffffffffu, pA, 1);
            pA += __shfl_xor_sync(0xffffffffu, pA, 2);
            pB += __shfl_xor_sync(0xffffffffu, pB, 1);
            pB += __shfl_xor_sync(0xffffffffu, pB, 2);
            if ((lane & 3) == 0) {
                int rA = wm0 + mt * 16 + (lane >> 2);
                atomicAdd(&red[rA], pA);
                atomicAdd(&red[rA + 8], pB);
            }
        }
        __syncthreads();
        if (tid < TM)
            Cm[bm + tid] = 1.0f / (1.0f + __expf(-(red[tid] + aux2[0])));
        return;
    }

    if (EPI == 3) {
        // fused gated combine, transposed store: out[b,c,l] = xw + mask*v
#pragma unroll
        for (int mt = 0; mt < MT; mt++) {
            const int row = bm + wm0 + mt * 16 + (lane >> 2);
#pragma unroll
            for (int rr = 0; rr < 2; rr++) {
                const int r = row + rr * 8;
                const int bb = r >> 10, l = r & 1023;
                const float mk = aux1[r];
#pragma unroll
                for (int nt = 0; nt < 4; nt++) {
                    const int col = bn + wn0 + nt * 8 + (lane & 3) * 2;
                    float2 bs = *(const float2*)(bias + col);
                    float v0 = c[mt][nt][rr*2 + 0] + bs.x;
                    float v1 = c[mt][nt][rr*2 + 1] + bs.y;
                    size_t o = ((size_t)(bb*CC + col)) * LL + l;
                    Cm[o]      = aux2[o]      + mk * v0;
                    Cm[o + LL] = aux2[o + LL] + mk * v1;
                }
            }
        }
        return;
    }

    // EPI == 0: plain biased store
#pragma unroll
    for (int mt = 0; mt < MT; mt++) {
        const int r0 = bm + wm0 + mt * 16 + (lane >> 2);
#pragma unroll
        for (int nt = 0; nt < 4; nt++) {
            const int col = bn + wn0 + nt * 8 + (lane & 3) * 2;
            float2 bs = *(const float2*)(bias + col);
            float v0 = c[mt][nt][0] + bs.x, v1 = c[mt][nt][1] + bs.y;
            float v2 = c[mt][nt][2] + bs.x, v3 = c[mt][nt][3] + bs.y;
            *(float2*)(Cm + (size_t)r0 * ldc + col)       = make_float2(v0, v1);
            *(float2*)(Cm + (size_t)(r0 + 8) * ldc + col) = make_float2(v2, v3);
        }
    }
}

// ---------------- weight rounding to bf16 (once per launch) -----------------
__global__ void round_weights(const float* __restrict__ ipw,
                              const float* __restrict__ opw,
                              const float* __restrict__ w1)
{
    int i = blockIdx.x * blockDim.x + threadIdx.x;
    const int N1 = 3*CC*CC, N2 = CC*CC, N3 = 128*2*CC;
    if (i < N1)            g_ipw[i] = __float2bfloat16_rn(ipw[i]);
    else if (i < N1 + N2)  g_opw[i - N1] = __float2bfloat16_rn(opw[i - N1]);
    else if (i < N1 + N2 + N3) g_w1[i - N1 - N2] = __float2bfloat16_rn(w1[i - N1 - N2]);
}

// ---------- fused walze + pack: conv/BN/GELU + transposed comb store --------
// Block = (b, ct: 32 channels, h: one row of 32 w). smem-staged 3-row x slab.
__global__ void __launch_bounds__(256)
walze_pack(const float* __restrict__ x,
           const float* __restrict__ dw_w,
           const float* __restrict__ dw_b,
           const float* __restrict__ sh_w,
           const float* __restrict__ sh_b,
           const float* __restrict__ mixw,
           const float* __restrict__ gamma,
           const float* __restrict__ beta)
{
    __shared__ float sx[32][97];    // [c][row3*32 + w], pad 97 for transpose reads
    __shared__ float swo[32][33];   // [w][c] staged x_walze for transposed store
    int bi = blockIdx.x;
    int h  = bi & 31, ct = (bi >> 5) & 15, b = bi >> 9;
    int c0 = ct * 32;
    int hm = (h + 31) & 31, hp = (h + 1) & 31;

    for (int i = threadIdx.x; i < 32 * 96; i += 256) {
        int w = i & 31, rs = (i >> 5) % 3, c = i / 96;
        int hr = (rs == 0) ? hm : ((rs == 1) ? h : hp);
        sx[c][rs * 32 + w] = x[((size_t)(b*CC + c0 + c)) * LL + hr * 32 + w];
    }
    __syncthreads();

    int tx = threadIdx.x & 31;     // w
    int tc = threadIdx.x >> 5;     // c stride-8 base
    int wm = (tx + 31) & 31, wp = (tx + 1) & 31;
    float mix = 1.0f / (1.0f + __expf(-mixw[0]));
    float sw0 = sh_w[0], sw1 = sh_w[1], sw2 = sh_w[2],
          sw3 = sh_w[3], sw4 = sh_w[4], sw5 = sh_w[5],
          sw6 = sh_w[6], sw7 = sh_w[7], sw8 = sh_w[8];
    float shb = sh_b[0];

#pragma unroll
    for (int k = 0; k < 4; k++) {
        int c = k * 8 + tc;
        float v00 = sx[c][wm],      v01 = sx[c][tx],      v02 = sx[c][wp];
        float v10 = sx[c][32 + wm], v11 = sx[c][32 + tx], v12 = sx[c][32 + wp];
        float v20 = sx[c][64 + wm], v21 = sx[c][64 + tx], v22 = sx[c][64 + wp];
        const float* dk = dw_w + (c0 + c) * 9;
        float mo = v00*dk[0] + v01*dk[1] + v02*dk[2]
                 + v10*dk[3] + v11*dk[4] + v12*dk[5]
                 + v20*dk[6] + v21*dk[7] + v22*dk[8] + dw_b[c0 + c];
        float ex = v00*sw0 + v01*sw1 + v02*sw2
                 + v10*sw3 + v11*sw4 + v12*sw5
                 + v20*sw6 + v21*sw7 + v22*sw8 + shb;
        float combined = mix * mo + (1.0f - mix) * ex + v11;
        float bn = gamma[c0 + c] * combined * rsqrtf(1.0f + 1e-5f) + beta[c0 + c];
        float xw = gelu_exact(bn);
        g_xwalze[((size_t)(b*CC + c0 + c)) * LL + h * 32 + tx] = xw;
        swo[tx][c] = xw;
    }
    __syncthreads();

    // transposed comb store: tx = c index, rows r = l-within-row
    int ty = threadIdx.x >> 5;
#pragma unroll
    for (int r = ty; r < 32; r += 8) {
        size_t dst = ((size_t)(b*LL + h*32 + r)) * (2*CC) + c0 + tx;
        g_comb[dst]      = __float2bfloat16_rn(sx[tx][32 + r]);  // x_before
        g_comb[dst + CC] = __float2bfloat16_rn(swo[r][tx]);      // x_after
    }
}

// ---------------- banded attention: smem-tiled, 2 queries per warp ----------
__global__ void __launch_bounds__(256)
attn_kernel()
{
    __shared__ float ks[96*64];
    __shared__ float vs[96*64];
    int bi = blockIdx.x;                   // 0..1023
    int qt = bi & 15;
    int h  = (bi >> 4) & 7;
    int b  = bi >> 7;
    int q0 = qt * 64;
    int jlo = max(0, q0 - WHALF);
    int jhi = min(LL - 1, q0 + 63 + WHALF);
    int nrows = jhi - jlo + 1;             // <= 96
    int tid = threadIdx.x;

    const float* kbase = g_qkv + (size_t)(b*LL + jlo) * (3*CC) + CC + h*HD;
    for (int i = tid; i < nrows * 16; i += 256) {
        int r = i >> 4, c = (i & 15) * 4;
        const float* kp = kbase + (size_t)r * (3*CC) + c;
        *(float4*)(ks + r*64 + c) = *(const float4*)kp;
        *(float4*)(vs + r*64 + c) = *(const float4*)(kp + CC);
    }
    __syncthreads();

    int wid = tid >> 5, lane = tid & 31;
    int half = lane >> 4;
    int dl = lane & 15;

#pragma unroll
    for (int pass = 0; pass < 4; pass++) {
        int qe = q0 + wid*8 + pass*2;
        int q  = qe + half;
        const float* qp = g_qkv + (size_t)(b*LL + q) * (3*CC) + h*HD + dl*4;
        float4 qv = *(const float4*)qp;
        qv.x *= 0.125f; qv.y *= 0.125f; qv.z *= 0.125f; qv.w *= 0.125f;

        int wlo = max(0, q - WHALF), whi = min(LL - 1, q + WHALF);
        int plo = max(0, qe - WHALF) - jlo;
        int phi = min(LL - 1, qe + 1 + WHALF) - jlo;

        float lsum = 0.0f;
        float4 acc = make_float4(0.f, 0.f, 0.f, 0.f);
        for (int j = plo; j <= phi; j++) {
            float4 kv = *(const float4*)(ks + j*64 + dl*4);
            float s = qv.x*kv.x + qv.y*kv.y + qv.z*kv.z + qv.w*kv.w;
            s += __shfl_xor_sync(0xffffffffu, s, 8);
            s += __shfl_xor_sync(0xffffffffu, s, 4);
            s += __shfl_xor_sync(0xffffffffu, s, 2);
            s += __shfl_xor_sync(0xffffffffu, s, 1);
            int gj = jlo + j;
            float p = (gj >= wlo && gj <= whi) ? __expf(s) : 0.0f;
            lsum += p;
            float4 vv = *(const float4*)(vs + j*64 + dl*4);
            acc.x += p*vv.x; acc.y += p*vv.y; acc.z += p*vv.z; acc.w += p*vv.w;
        }
        float inv = 1.0f / lsum;
        __nv_bfloat16* op = g_ctx + (size_t)(b*LL + q) * CC + h*HD + dl*4;
        __nv_bfloat162 o01 = __floats2bfloat162_rn(acc.x * inv, acc.y * inv);
        __nv_bfloat162 o23 = __floats2bfloat162_rn(acc.z * inv, acc.w * inv);
        *(uint2*)op = make_uint2(*(uint32_t*)&o01, *(uint32_t*)&o23);
    }
}

// ---------------- host launcher ---------------------------------------------
extern "C" void kernel_launch(void* const* d_in, const int* in_sizes, int n_in,
                              void* d_out, int out_size)
{
    const float* x      = (const float*)d_in[0];
    const float* dw_w   = (const float*)d_in[1];
    const float* dw_b   = (const float*)d_in[2];
    const float* sh_w   = (const float*)d_in[3];
    const float* sh_b   = (const float*)d_in[4];
    const float* mixw   = (const float*)d_in[5];
    const float* gamma  = (const float*)d_in[6];
    const float* beta   = (const float*)d_in[7];
    const float* det_w1 = (const float*)d_in[8];
    const float* det_b1 = (const float*)d_in[9];
    const float* det_w2 = (const float*)d_in[10];
    const float* det_b2 = (const float*)d_in[11];
    const float* ipw    = (const float*)d_in[12];
    const float* ipb    = (const float*)d_in[13];
    const float* opw    = (const float*)d_in[14];
    const float* opb    = (const float*)d_in[15];
    float* out = (float*)d_out;

    __nv_bfloat16 *p_comb, *p_ctx, *p_ipw, *p_opw, *p_w1;
    float *p_qkv, *p_mask, *p_xwalze;
    cudaGetSymbolAddress((void**)&p_comb,   g_comb);
    cudaGetSymbolAddress((void**)&p_qkv,    g_qkv);
    cudaGetSymbolAddress((void**)&p_ctx,    g_ctx);
    cudaGetSymbolAddress((void**)&p_ipw,    g_ipw);
    cudaGetSymbolAddress((void**)&p_opw,    g_opw);
    cudaGetSymbolAddress((void**)&p_w1,     g_w1);
    cudaGetSymbolAddress((void**)&p_mask,   g_mask);
    cudaGetSymbolAddress((void**)&p_xwalze, g_xwalze);

    const int SMEM128 = 2 * (128*128 + 16384);   // 65536
    const int SMEM64  = 2 * (64*128  + 16384);   // 49152
    cudaFuncSetAttribute((const void*)mma_gemm<0,4>,
                         cudaFuncAttributeMaxDynamicSharedMemorySize, SMEM128);
    cudaFuncSetAttribute((const void*)mma_gemm<3,4>,
                         cudaFuncAttributeMaxDynamicSharedMemorySize, SMEM128);
    cudaFuncSetAttribute((const void*)mma_gemm<2,2>,
                         cudaFuncAttributeMaxDynamicSharedMemorySize, SMEM64);

    const int M = BB*LL;            // 8192

    // 0) round weights to bf16 once
    {
        int tot = 3*CC*CC + CC*CC + 128*2*CC;
        round_weights<<<(tot + 255)/256, 256>>>(ipw, opw, det_w1);
    }

    // 1) fused walze + pack
    walze_pack<<<BB*16*32, 256>>>(x, dw_w, dw_b, sh_w, sh_b, mixw, gamma, beta);

    // 2) detector GEMM + head fused -> mask
    {
        dim3 g(1, M/64);
        mma_gemm<2,2><<<g, 256, SMEM64>>>(p_comb, 2*CC, p_w1, 2*CC,
                                          det_b1, p_mask, 1, 2*CC,
                                          det_w2, det_b2);
    }

    // 3) QKV GEMM: qkv = x_after(8192,512) @ in_proj_w^T(512,1536) + b
    {
        dim3 g((3*CC)/128, M/128);
        mma_gemm<0,4><<<g, 256, SMEM128>>>(p_comb + CC, 2*CC, p_ipw, CC,
                                           ipb, p_qkv, 3*CC, CC,
                                           nullptr, nullptr);
    }

    // 4) banded attention (smem-tiled)
    attn_kernel<<<BB*NHD*(LL/64), 256>>>();

    // 5) out_proj GEMM + gated combine fused -> out
    {
        dim3 g(CC/128, M/128);
        mma_gemm<3,4><<<g, 256, SMEM128>>>(p_ctx, CC, p_opw, CC,
                                           opb, out, 0, CC,
                                           p_mask, p_xwalze);
    }
}

// round 7
// speedup vs baseline: 1.0456x; 1.0456x over previous
#include <cuda_runtime.h>
#include <cuda_bf16.h>
#include <math.h>
#include <stdint.h>

#define BB 8
#define CC 512
#define HH 32
#define WW 32
#define LL 1024   // H*W
#define NHD 8
#define HD 64
#define WHALF 16  // WINDOW/2

// ---------------- scratch (static device globals; no runtime allocation) ----
__device__ float g_xwalze[BB*CC*HH*WW];          // (B,C,H,W) post-walze
__device__ __nv_bfloat16 g_comb[BB*LL*2*CC];     // (B*L, 2C): [before | after]
__device__ float g_mask[BB*LL];                  // soft mask
__device__ float g_qkv[BB*LL*3*CC];              // (B*L, 3C)
__device__ __nv_bfloat16 g_ctx[BB*LL*CC];        // attention context (bf16)
__device__ float g_attnout[BB*LL*CC];            // out_proj result (B*L, C)
__device__ __nv_bfloat16 g_ipw[3*CC*CC];         // bf16 in_proj_w
__device__ __nv_bfloat16 g_opw[CC*CC];           // bf16 out_proj_w
__device__ __nv_bfloat16 g_w1[128*2*CC];         // bf16 det_w1

__device__ __forceinline__ float gelu_exact(float v) {
    return 0.5f * v * (1.0f + erff(v * 0.70710678118654752440f));
}
__device__ __forceinline__ uint32_t smem_u32(const void* p) {
    uint32_t a;
    asm("{ .reg .u64 t; cvta.to.shared.u64 t, %1; cvt.u32.u64 %0, t; }"
        : "=r"(a) : "l"(p));
    return a;
}
__device__ __forceinline__ void cp16(uint32_t dst, const void* src) {
    asm volatile("cp.async.cg.shared.global [%0], [%1], 16;" :: "r"(dst), "l"(src));
}
__device__ __forceinline__ void ldmx4(uint32_t addr, uint32_t& r0, uint32_t& r1,
                                      uint32_t& r2, uint32_t& r3) {
    asm volatile("ldmatrix.sync.aligned.m8n8.x4.shared.b16 {%0,%1,%2,%3}, [%4];"
                 : "=r"(r0), "=r"(r1), "=r"(r2), "=r"(r3) : "r"(addr));
}
__device__ __forceinline__ void mma16(float* c, uint32_t a0, uint32_t a1,
                                      uint32_t a2, uint32_t a3,
                                      uint32_t b0, uint32_t b1) {
    asm volatile("mma.sync.aligned.m16n8k16.row.col.f32.bf16.bf16.f32 "
                 "{%0,%1,%2,%3}, {%4,%5,%6,%7}, {%8,%9}, {%0,%1,%2,%3};"
                 : "+f"(c[0]), "+f"(c[1]), "+f"(c[2]), "+f"(c[3])
                 : "r"(a0), "r"(a1), "r"(a2), "r"(a3), "r"(b0), "r"(b1));
}

// ====== bf16 mma.sync GEMM: C(M,N) = A(M,K) * B(N,K)^T + bias ===============
// CTA tile (MT*32) x 128, 8 warps (2 m x 4 n). K-chunk 64 bf16 (128B rows),
// 3-stage cp.async pipeline (ONE barrier per chunk), xor-swizzled smem.
// EPI: 0 = plain biased store, 2 = detector head (gelu . w2 -> sigmoid).
template<int EPI, int MT>
__global__ void __launch_bounds__(256, 2)
mma_gemm(const __nv_bfloat16* __restrict__ A, int lda,
         const __nv_bfloat16* __restrict__ Bm, int ldb,
         const float* __restrict__ bias,
         float* __restrict__ Cm, int ldc, int K,
         const float* __restrict__ aux1,   // EPI2: w2
         const float* __restrict__ aux2)   // EPI2: b2
{
    constexpr int TM = MT * 32;
    constexpr int ABYTES = TM * 128;
    constexpr int BUFB = ABYTES + 16384;
    extern __shared__ char smem[];
    const uint32_t sb = smem_u32(smem);
    const int tid = threadIdx.x, lane = tid & 31, wid = tid >> 5;
    const int bm = blockIdx.y * TM, bn = blockIdx.x * 128;
    const int wm0 = (wid & 1) * (TM / 2), wn0 = (wid >> 1) * 32;

    const int ld_row = tid >> 3;
    const uint32_t st_off =
        (uint32_t)(ld_row * 128 + (((tid & 7) * 16) ^ ((ld_row & 7) << 4)));
    const __nv_bfloat16* Agb = A  + (size_t)(bm + ld_row) * lda + (tid & 7) * 8;
    const __nv_bfloat16* Bgb = Bm + (size_t)(bn + ld_row) * ldb + (tid & 7) * 8;

    auto load_tile = [&](int buf, int ch) {
        uint32_t da = sb + buf * BUFB + st_off;
        uint32_t db = da + ABYTES;
        const __nv_bfloat16* sa  = Agb + ch * 64;
        const __nv_bfloat16* sbp = Bgb + ch * 64;
#pragma unroll
        for (int p = 0; p < MT; p++)
            cp16(da + p * 4096, sa + (size_t)p * 32 * lda);
#pragma unroll
        for (int p = 0; p < 4; p++)
            cp16(db + p * 4096, sbp + (size_t)p * 32 * ldb);
        asm volatile("cp.async.commit_group;" ::: "memory");
    };

    const int arow  = wm0 + (lane & 15);
    const uint32_t akb = ((uint32_t)(lane >> 4)) << 4;
    const uint32_t aswz = (uint32_t)((arow & 7) << 4);
    const uint32_t a_rowbase = (uint32_t)(arow * 128);
    const int brow  = wn0 + ((lane >> 4) << 3) + (lane & 7);
    const uint32_t bkb = (uint32_t)(((lane >> 3) & 1) << 4);
    const uint32_t bswz = (uint32_t)((brow & 7) << 4);
    const uint32_t b_rowbase = (uint32_t)(ABYTES + brow * 128);

    float c[MT][4][4];
#pragma unroll
    for (int i = 0; i < MT; i++)
#pragma unroll
        for (int j = 0; j < 4; j++)
#pragma unroll
            for (int k = 0; k < 4; k++) c[i][j][k] = 0.0f;

    const int nch = K >> 6;
    load_tile(0, 0);
    load_tile(1, 1);

    for (int ch = 0; ch < nch; ch++) {
        const int buf = ch % 3;
        if (ch + 1 < nch) asm volatile("cp.async.wait_group 1;" ::: "memory");
        else              asm volatile("cp.async.wait_group 0;" ::: "memory");
        __syncthreads();
        // issue next load first: target buffer (ch+2)%3 == (ch-1)%3 was fully
        // consumed in iteration ch-1, protected by the barrier just crossed.
        if (ch + 2 < nch) load_tile((ch + 2) % 3, ch + 2);

        const uint32_t base = sb + buf * BUFB;
#pragma unroll
        for (int ks = 0; ks < 4; ks++) {
            const uint32_t kso = (uint32_t)(ks * 32);
            uint32_t a[MT][4];
#pragma unroll
            for (int mt = 0; mt < MT; mt++)
                ldmx4(base + a_rowbase + (uint32_t)(mt * 2048) + ((kso + akb) ^ aswz),
                      a[mt][0], a[mt][1], a[mt][2], a[mt][3]);
            uint32_t b[4][2];
#pragma unroll
            for (int nt2 = 0; nt2 < 2; nt2++)
                ldmx4(base + b_rowbase + (uint32_t)(nt2 * 2048) + ((kso + bkb) ^ bswz),
                      b[nt2*2][0], b[nt2*2][1], b[nt2*2+1][0], b[nt2*2+1][1]);
#pragma unroll
            for (int mt = 0; mt < MT; mt++)
#pragma unroll
                for (int nt = 0; nt < 4; nt++)
                    mma16(c[mt][nt], a[mt][0], a[mt][1], a[mt][2], a[mt][3],
                          b[nt][0], b[nt][1]);
        }
    }

    if (EPI == 2) {
        // detector head: logit[r] = sum_col gelu(v+b1)[r,col] * w2[col]
        float* red = (float*)smem;
        __syncthreads();
        if (tid < TM) red[tid] = 0.0f;
        __syncthreads();
#pragma unroll
        for (int mt = 0; mt < MT; mt++) {
            float pA = 0.0f, pB = 0.0f;
#pragma unroll
            for (int nt = 0; nt < 4; nt++) {
                int col = bn + wn0 + nt * 8 + (lane & 3) * 2;
                float2 bs = *(const float2*)(bias + col);
                float w0 = aux1[col], w1 = aux1[col + 1];
                pA += gelu_exact(c[mt][nt][0] + bs.x) * w0
                    + gelu_exact(c[mt][nt][1] + bs.y) * w1;
                pB += gelu_exact(c[mt][nt][2] + bs.x) * w0
                    + gelu_exact(c[mt][nt][3] + bs.y) * w1;
            }
            pA += __shfl_xor_sync(0xffffffffu, pA, 1);
            pA += __shfl_xor_sync(0xffffffffu, pA, 2);
            pB += __shfl_xor_sync(0xffffffffu, pB, 1);
            pB += __shfl_xor_sync(0xffffffffu, pB, 2);
            if ((lane & 3) == 0) {
                int rA = wm0 + mt * 16 + (lane >> 2);
                atomicAdd(&red[rA], pA);
                atomicAdd(&red[rA + 8], pB);
            }
        }
        __syncthreads();
        if (tid < TM)
            Cm[bm + tid] = 1.0f / (1.0f + __expf(-(red[tid] + aux2[0])));
        return;
    }

    // EPI == 0: plain biased store
#pragma unroll
    for (int mt = 0; mt < MT; mt++) {
        const int r0 = bm + wm0 + mt * 16 + (lane >> 2);
#pragma unroll
        for (int nt = 0; nt < 4; nt++) {
            const int col = bn + wn0 + nt * 8 + (lane & 3) * 2;
            float2 bs = *(const float2*)(bias + col);
            float v0 = c[mt][nt][0] + bs.x, v1 = c[mt][nt][1] + bs.y;
            float v2 = c[mt][nt][2] + bs.x, v3 = c[mt][nt][3] + bs.y;
            *(float2*)(Cm + (size_t)r0 * ldc + col)       = make_float2(v0, v1);
            *(float2*)(Cm + (size_t)(r0 + 8) * ldc + col) = make_float2(v2, v3);
        }
    }
}

// ---------------- weight rounding to bf16 (once per launch) -----------------
__global__ void round_weights(const float* __restrict__ ipw,
                              const float* __restrict__ opw,
                              const float* __restrict__ w1)
{
    int i = blockIdx.x * blockDim.x + threadIdx.x;
    const int N1 = 3*CC*CC, N2 = CC*CC, N3 = 128*2*CC;
    if (i < N1)            g_ipw[i] = __float2bfloat16_rn(ipw[i]);
    else if (i < N1 + N2)  g_opw[i - N1] = __float2bfloat16_rn(opw[i - N1]);
    else if (i < N1 + N2 + N3) g_w1[i - N1 - N2] = __float2bfloat16_rn(w1[i - N1 - N2]);
}

// ---------------- kernel 1: dual depthwise conv + residual + BN + GELU ------
__global__ void walze_kernel(const float* __restrict__ x,
                             const float* __restrict__ dw_w,
                             const float* __restrict__ dw_b,
                             const float* __restrict__ sh_w,
                             const float* __restrict__ sh_b,
                             const float* __restrict__ mixw,
                             const float* __restrict__ gamma,
                             const float* __restrict__ beta)
{
    int idx = blockIdx.x * blockDim.x + threadIdx.x;
    if (idx >= BB*CC*HH*WW) return;
    int w = idx & 31;
    int h = (idx >> 5) & 31;
    int c = (idx >> 10) & 511;
    int b = idx >> 19;

    const float* xb = x + ((size_t)(b*CC + c)) * (HH*WW);
    int hm = (h + HH - 1) & 31, hp = (h + 1) & 31;
    int wm = (w + WW - 1) & 31, wp = (w + 1) & 31;

    float v00 = xb[hm*WW+wm], v01 = xb[hm*WW+w], v02 = xb[hm*WW+wp];
    float v10 = xb[h *WW+wm], v11 = xb[h *WW+w], v12 = xb[h *WW+wp];
    float v20 = xb[hp*WW+wm], v21 = xb[hp*WW+w], v22 = xb[hp*WW+wp];

    const float* dk = dw_w + c*9;
    float main_out = v00*dk[0] + v01*dk[1] + v02*dk[2]
                   + v10*dk[3] + v11*dk[4] + v12*dk[5]
                   + v20*dk[6] + v21*dk[7] + v22*dk[8] + dw_b[c];
    float ex = v00*sh_w[0] + v01*sh_w[1] + v02*sh_w[2]
             + v10*sh_w[3] + v11*sh_w[4] + v12*sh_w[5]
             + v20*sh_w[6] + v21*sh_w[7] + v22*sh_w[8] + sh_b[0];

    float mix = 1.0f / (1.0f + __expf(-mixw[0]));
    float combined = mix * main_out + (1.0f - mix) * ex + v11;
    float bn = gamma[c] * combined * rsqrtf(1.0f + 1e-5f) + beta[c];
    g_xwalze[idx] = gelu_exact(bn);
}

// ---------------- pack: transpose x / x_walze into comb rows (bf16) ---------
__global__ void __launch_bounds__(256)
pack_kernel(const float* __restrict__ x)
{
    __shared__ float sx[32][33];
    __shared__ float sw[32][33];
    int bi = blockIdx.x;
    int lt = bi & 31, ct = (bi >> 5) & 15, b = bi >> 9;
    int c0 = ct * 32, l0 = lt * 32;
    int tx = threadIdx.x & 31, ty = threadIdx.x >> 5;
#pragma unroll
    for (int r = ty; r < 32; r += 8) {
        size_t src = (size_t)(b*CC + c0 + r) * LL + l0 + tx;
        sx[r][tx] = x[src];
        sw[r][tx] = g_xwalze[src];
    }
    __syncthreads();
#pragma unroll
    for (int r = ty; r < 32; r += 8) {   // r = local l index
        size_t dst = (size_t)(b*LL + l0 + r) * (2*CC) + c0 + tx;
        g_comb[dst]      = __float2bfloat16_rn(sx[tx][r]);
        g_comb[dst + CC] = __float2bfloat16_rn(sw[tx][r]);
    }
}

// ---------------- banded attention: smem-tiled, 2 queries per warp ----------
__global__ void __launch_bounds__(256)
attn_kernel()
{
    __shared__ float ks[96*64];
    __shared__ float vs[96*64];
    int bi = blockIdx.x;                   // 0..1023
    int qt = bi & 15;
    int h  = (bi >> 4) & 7;
    int b  = bi >> 7;
    int q0 = qt * 64;
    int jlo = max(0, q0 - WHALF);
    int jhi = min(LL - 1, q0 + 63 + WHALF);
    int nrows = jhi - jlo + 1;             // <= 96
    int tid = threadIdx.x;

    const float* kbase = g_qkv + (size_t)(b*LL + jlo) * (3*CC) + CC + h*HD;
    for (int i = tid; i < nrows * 16; i += 256) {
        int r = i >> 4, c = (i & 15) * 4;
        const float* kp = kbase + (size_t)r * (3*CC) + c;
        *(float4*)(ks + r*64 + c) = *(const float4*)kp;
        *(float4*)(vs + r*64 + c) = *(const float4*)(kp + CC);
    }
    __syncthreads();

    int wid = tid >> 5, lane = tid & 31;
    int half = lane >> 4;
    int dl = lane & 15;

#pragma unroll
    for (int pass = 0; pass < 4; pass++) {
        int qe = q0 + wid*8 + pass*2;
        int q  = qe + half;
        const float* qp = g_qkv + (size_t)(b*LL + q) * (3*CC) + h*HD + dl*4;
        float4 qv = *(const float4*)qp;
        qv.x *= 0.125f; qv.y *= 0.125f; qv.z *= 0.125f; qv.w *= 0.125f;

        int wlo = max(0, q - WHALF), whi = min(LL - 1, q + WHALF);
        int plo = max(0, qe - WHALF) - jlo;
        int phi = min(LL - 1, qe + 1 + WHALF) - jlo;

        float lsum = 0.0f;
        float4 acc = make_float4(0.f, 0.f, 0.f, 0.f);
        for (int j = plo; j <= phi; j++) {
            float4 kv = *(const float4*)(ks + j*64 + dl*4);
            float s = qv.x*kv.x + qv.y*kv.y + qv.z*kv.z + qv.w*kv.w;
            s += __shfl_xor_sync(0xffffffffu, s, 8);
            s += __shfl_xor_sync(0xffffffffu, s, 4);
            s += __shfl_xor_sync(0xffffffffu, s, 2);
            s += __shfl_xor_sync(0xffffffffu, s, 1);
            int gj = jlo + j;
            float p = (gj >= wlo && gj <= whi) ? __expf(s) : 0.0f;
            lsum += p;
            float4 vv = *(const float4*)(vs + j*64 + dl*4);
            acc.x += p*vv.x; acc.y += p*vv.y; acc.z += p*vv.z; acc.w += p*vv.w;
        }
        float inv = 1.0f / lsum;
        __nv_bfloat16* op = g_ctx + (size_t)(b*LL + q) * CC + h*HD + dl*4;
        __nv_bfloat162 o01 = __floats2bfloat162_rn(acc.x * inv, acc.y * inv);
        __nv_bfloat162 o23 = __floats2bfloat162_rn(acc.z * inv, acc.w * inv);
        *(uint2*)op = make_uint2(*(uint32_t*)&o01, *(uint32_t*)&o23);
    }
}

// ---------------- gated residual combine: smem-transposed, coalesced --------
__global__ void __launch_bounds__(256)
combine_kernel(float* __restrict__ out)
{
    __shared__ float s[32][33];
    int bi = blockIdx.x;
    int ct = bi & 15, lt = (bi >> 4) & 31, b = bi >> 9;
    int c0 = ct * 32, l0 = lt * 32;
    int tx = threadIdx.x & 31, ty = threadIdx.x >> 5;
#pragma unroll
    for (int r = ty; r < 32; r += 8)
        s[r][tx] = g_attnout[(size_t)(b*LL + l0 + r) * CC + c0 + tx];
    __syncthreads();
    float mk = g_mask[b*LL + l0 + tx];
#pragma unroll
    for (int cr = ty; cr < 32; cr += 8) {
        size_t o = (size_t)(b*CC + c0 + cr) * LL + l0 + tx;
        out[o] = g_xwalze[o] + mk * s[tx][cr];
    }
}

// ---------------- host launcher ---------------------------------------------
extern "C" void kernel_launch(void* const* d_in, const int* in_sizes, int n_in,
                              void* d_out, int out_size)
{
    const float* x      = (const float*)d_in[0];
    const float* dw_w   = (const float*)d_in[1];
    const float* dw_b   = (const float*)d_in[2];
    const float* sh_w   = (const float*)d_in[3];
    const float* sh_b   = (const float*)d_in[4];
    const float* mixw   = (const float*)d_in[5];
    const float* gamma  = (const float*)d_in[6];
    const float* beta   = (const float*)d_in[7];
    const float* det_w1 = (const float*)d_in[8];
    const float* det_b1 = (const float*)d_in[9];
    const float* det_w2 = (const float*)d_in[10];
    const float* det_b2 = (const float*)d_in[11];
    const float* ipw    = (const float*)d_in[12];
    const float* ipb    = (const float*)d_in[13];
    const float* opw    = (const float*)d_in[14];
    const float* opb    = (const float*)d_in[15];
    float* out = (float*)d_out;

    __nv_bfloat16 *p_comb, *p_ctx, *p_ipw, *p_opw, *p_w1;
    float *p_qkv, *p_mask, *p_attnout;
    cudaGetSymbolAddress((void**)&p_comb,    g_comb);
    cudaGetSymbolAddress((void**)&p_qkv,     g_qkv);
    cudaGetSymbolAddress((void**)&p_ctx,     g_ctx);
    cudaGetSymbolAddress((void**)&p_ipw,     g_ipw);
    cudaGetSymbolAddress((void**)&p_opw,     g_opw);
    cudaGetSymbolAddress((void**)&p_w1,      g_w1);
    cudaGetSymbolAddress((void**)&p_mask,    g_mask);
    cudaGetSymbolAddress((void**)&p_attnout, g_attnout);

    const int SMEM128 = 3 * (128*128 + 16384);   // 98304
    const int SMEM64  = 3 * (64*128  + 16384);   // 73728
    cudaFuncSetAttribute((const void*)mma_gemm<0,4>,
                         cudaFuncAttributeMaxDynamicSharedMemorySize, SMEM128);
    cudaFuncSetAttribute((const void*)mma_gemm<2,2>,
                         cudaFuncAttributeMaxDynamicSharedMemorySize, SMEM64);

    const int NTOT = BB*CC*HH*WW;   // 4,194,304
    const int M = BB*LL;            // 8192

    // 0) round weights to bf16 once
    {
        int tot = 3*CC*CC + CC*CC + 128*2*CC;
        round_weights<<<(tot + 255)/256, 256>>>(ipw, opw, det_w1);
    }

    // 1) walze: dwconv + BN + GELU (spatial layout only)
    walze_kernel<<<NTOT/256, 256>>>(x, dw_w, dw_b, sh_w, sh_b, mixw, gamma, beta);

    // 1b) pack: transpose into comb rows (bf16), fully coalesced
    pack_kernel<<<BB*16*32, 256>>>(x);

    // 2) detector GEMM + head fused -> mask
    {
        dim3 g(1, M/64);
        mma_gemm<2,2><<<g, 256, SMEM64>>>(p_comb, 2*CC, p_w1, 2*CC,
                                          det_b1, p_mask, 1, 2*CC,
                                          det_w2, det_b2);
    }

    // 3) QKV GEMM: qkv = x_after(8192,512) @ in_proj_w^T(512,1536) + b
    {
        dim3 g((3*CC)/128, M/128);
        mma_gemm<0,4><<<g, 256, SMEM128>>>(p_comb + CC, 2*CC, p_ipw, CC,
                                           ipb, p_qkv, 3*CC, CC,
                                           nullptr, nullptr);
    }

    // 4) banded attention (smem-tiled)
    attn_kernel<<<BB*NHD*(LL/64), 256>>>();

    // 5) out_proj GEMM: N=512, K=512
    {
        dim3 g(CC/128, M/128);
        mma_gemm<0,4><<<g, 256, SMEM128>>>(p_ctx, CC, p_opw, CC,
                                           opb, p_attnout, CC, CC,
                                           nullptr, nullptr);
    }

    // 6) gated residual combine (transposed, coalesced)
    combine_kernel<<<BB*16*32, 256>>>(out);
}

// round 8
// speedup vs baseline: 1.1600x; 1.1094x over previous
#include <cuda_runtime.h>
#include <cuda_bf16.h>
#include <math.h>
#include <stdint.h>

#define BB 8
#define CC 512
#define HH 32
#define WW 32
#define LL 1024   // H*W
#define NHD 8
#define HD 64
#define WHALF 16  // WINDOW/2

// ---------------- scratch (static device globals; no runtime allocation) ----
__device__ float g_xwalze[BB*CC*HH*WW];          // (B,C,H,W) post-walze
__device__ __nv_bfloat16 g_comb[BB*LL*2*CC];     // (B*L, 2C): [before | after]
__device__ float g_mask[BB*LL];                  // soft mask
__device__ float g_qkv[BB*LL*3*CC];              // (B*L, 3C)
__device__ __nv_bfloat16 g_ctx[BB*LL*CC];        // attention context (bf16)
__device__ float g_attnout[BB*LL*CC];            // out_proj result (B*L, C)
__device__ __nv_bfloat16 g_ipw[3*CC*CC];         // bf16 in_proj_w
__device__ __nv_bfloat16 g_opw[CC*CC];           // bf16 out_proj_w
__device__ __nv_bfloat16 g_w1[128*2*CC];         // bf16 det_w1

__device__ __forceinline__ float gelu_exact(float v) {
    return 0.5f * v * (1.0f + erff(v * 0.70710678118654752440f));
}
__device__ __forceinline__ uint32_t smem_u32(const void* p) {
    uint32_t a;
    asm("{ .reg .u64 t; cvta.to.shared.u64 t, %1; cvt.u32.u64 %0, t; }"
        : "=r"(a) : "l"(p));
    return a;
}
__device__ __forceinline__ void cp16(uint32_t dst, const void* src) {
    asm volatile("cp.async.cg.shared.global [%0], [%1], 16;" :: "r"(dst), "l"(src));
}
__device__ __forceinline__ void ldmx4(uint32_t addr, uint32_t& r0, uint32_t& r1,
                                      uint32_t& r2, uint32_t& r3) {
    asm volatile("ldmatrix.sync.aligned.m8n8.x4.shared.b16 {%0,%1,%2,%3}, [%4];"
                 : "=r"(r0), "=r"(r1), "=r"(r2), "=r"(r3) : "r"(addr));
}
__device__ __forceinline__ void mma16(float* c, uint32_t a0, uint32_t a1,
                                      uint32_t a2, uint32_t a3,
                                      uint32_t b0, uint32_t b1) {
    asm volatile("mma.sync.aligned.m16n8k16.row.col.f32.bf16.bf16.f32 "
                 "{%0,%1,%2,%3}, {%4,%5,%6,%7}, {%8,%9}, {%0,%1,%2,%3};"
                 : "+f"(c[0]), "+f"(c[1]), "+f"(c[2]), "+f"(c[3])
                 : "r"(a0), "r"(a1), "r"(a2), "r"(a3), "r"(b0), "r"(b1));
}

// ====== bf16 mma.sync GEMM body: C(M,N) = A(M,K)*B(N,K)^T + bias ============
// CTA tile (MT*32) x 128, 8 warps (2 m x 4 n). K-chunk 64 bf16 (128B rows),
// 3-stage cp.async pipeline, xor-swizzled smem.
// EPI: 0 = plain biased store, 2 = detector head (gelu . w2 -> sigmoid).
template<int EPI, int MT>
__device__ __forceinline__ void
gemm_body(int bm, int bn,
          const __nv_bfloat16* __restrict__ A, int lda,
          const __nv_bfloat16* __restrict__ Bm, int ldb,
          const float* __restrict__ bias,
          float* __restrict__ Cm, int ldc, int K,
          const float* __restrict__ aux1,   // EPI2: w2
          const float* __restrict__ aux2,   // EPI2: b2
          char* smem)
{
    constexpr int TM = MT * 32;
    constexpr int ABYTES = TM * 128;
    constexpr int BUFB = ABYTES + 16384;
    const uint32_t sb = smem_u32(smem);
    const int tid = threadIdx.x, lane = tid & 31, wid = tid >> 5;
    const int wm0 = (wid & 1) * (TM / 2), wn0 = (wid >> 1) * 32;

    const int ld_row = tid >> 3;
    const uint32_t st_off =
        (uint32_t)(ld_row * 128 + (((tid & 7) * 16) ^ ((ld_row & 7) << 4)));
    const __nv_bfloat16* Agb = A  + (size_t)(bm + ld_row) * lda + (tid & 7) * 8;
    const __nv_bfloat16* Bgb = Bm + (size_t)(bn + ld_row) * ldb + (tid & 7) * 8;

    auto load_tile = [&](int buf, int ch) {
        uint32_t da = sb + buf * BUFB + st_off;
        uint32_t db = da + ABYTES;
        const __nv_bfloat16* sa  = Agb + ch * 64;
        const __nv_bfloat16* sbp = Bgb + ch * 64;
#pragma unroll
        for (int p = 0; p < MT; p++)
            cp16(da + p * 4096, sa + (size_t)p * 32 * lda);
#pragma unroll
        for (int p = 0; p < 4; p++)
            cp16(db + p * 4096, sbp + (size_t)p * 32 * ldb);
        asm volatile("cp.async.commit_group;" ::: "memory");
    };

    const int arow  = wm0 + (lane & 15);
    const uint32_t akb = ((uint32_t)(lane >> 4)) << 4;
    const uint32_t aswz = (uint32_t)((arow & 7) << 4);
    const uint32_t a_rowbase = (uint32_t)(arow * 128);
    const int brow  = wn0 + ((lane >> 4) << 3) + (lane & 7);
    const uint32_t bkb = (uint32_t)(((lane >> 3) & 1) << 4);
    const uint32_t bswz = (uint32_t)((brow & 7) << 4);
    const uint32_t b_rowbase = (uint32_t)(ABYTES + brow * 128);

    float c[MT][4][4];
#pragma unroll
    for (int i = 0; i < MT; i++)
#pragma unroll
        for (int j = 0; j < 4; j++)
#pragma unroll
            for (int k = 0; k < 4; k++) c[i][j][k] = 0.0f;

    const int nch = K >> 6;
    load_tile(0, 0);
    load_tile(1, 1);

    for (int ch = 0; ch < nch; ch++) {
        const int buf = ch % 3;
        if (ch + 1 < nch) asm volatile("cp.async.wait_group 1;" ::: "memory");
        else              asm volatile("cp.async.wait_group 0;" ::: "memory");
        __syncthreads();
        if (ch + 2 < nch) load_tile((ch + 2) % 3, ch + 2);

        const uint32_t base = sb + buf * BUFB;
#pragma unroll
        for (int ks = 0; ks < 4; ks++) {
            const uint32_t kso = (uint32_t)(ks * 32);
            uint32_t a[MT][4];
#pragma unroll
            for (int mt = 0; mt < MT; mt++)
                ldmx4(base + a_rowbase + (uint32_t)(mt * 2048) + ((kso + akb) ^ aswz),
                      a[mt][0], a[mt][1], a[mt][2], a[mt][3]);
            uint32_t b[4][2];
#pragma unroll
            for (int nt2 = 0; nt2 < 2; nt2++)
                ldmx4(base + b_rowbase + (uint32_t)(nt2 * 2048) + ((kso + bkb) ^ bswz),
                      b[nt2*2][0], b[nt2*2][1], b[nt2*2+1][0], b[nt2*2+1][1]);
#pragma unroll
            for (int mt = 0; mt < MT; mt++)
#pragma unroll
                for (int nt = 0; nt < 4; nt++)
                    mma16(c[mt][nt], a[mt][0], a[mt][1], a[mt][2], a[mt][3],
                          b[nt][0], b[nt][1]);
        }
    }

    if (EPI == 2) {
        float* red = (float*)smem;
        __syncthreads();
        if (tid < TM) red[tid] = 0.0f;
        __syncthreads();
#pragma unroll
        for (int mt = 0; mt < MT; mt++) {
            float pA = 0.0f, pB = 0.0f;
#pragma unroll
            for (int nt = 0; nt < 4; nt++) {
                int col = bn + wn0 + nt * 8 + (lane & 3) * 2;
                float2 bs = *(const float2*)(bias + col);
                float w0 = aux1[col], w1 = aux1[col + 1];
                pA += gelu_exact(c[mt][nt][0] + bs.x) * w0
                    + gelu_exact(c[mt][nt][1] + bs.y) * w1;
                pB += gelu_exact(c[mt][nt][2] + bs.x) * w0
                    + gelu_exact(c[mt][nt][3] + bs.y) * w1;
            }
            pA += __shfl_xor_sync(0xffffffffu, pA, 1);
            pA += __shfl_xor_sync(0xffffffffu, pA, 2);
            pB += __shfl_xor_sync(0xffffffffu, pB, 1);
            pB += __shfl_xor_sync(0xffffffffu, pB, 2);
            if ((lane & 3) == 0) {
                int rA = wm0 + mt * 16 + (lane >> 2);
                atomicAdd(&red[rA], pA);
                atomicAdd(&red[rA + 8], pB);
            }
        }
        __syncthreads();
        if (tid < TM)
            Cm[bm + tid] = 1.0f / (1.0f + __expf(-(red[tid] + aux2[0])));
        return;
    }

    // EPI == 0: plain biased store
#pragma unroll
    for (int mt = 0; mt < MT; mt++) {
        const int r0 = bm + wm0 + mt * 16 + (lane >> 2);
#pragma unroll
        for (int nt = 0; nt < 4; nt++) {
            const int col = bn + wn0 + nt * 8 + (lane & 3) * 2;
            float2 bs = *(const float2*)(bias + col);
            float v0 = c[mt][nt][0] + bs.x, v1 = c[mt][nt][1] + bs.y;
            float v2 = c[mt][nt][2] + bs.x, v3 = c[mt][nt][3] + bs.y;
            *(float2*)(Cm + (size_t)r0 * ldc + col)       = make_float2(v0, v1);
            *(float2*)(Cm + (size_t)(r0 + 8) * ldc + col) = make_float2(v2, v3);
        }
    }
}

// ---- fused launch: QKV GEMM (768 CTAs) + detector GEMM+head (128 CTAs) -----
#define QKV_BLOCKS 768
__global__ void __launch_bounds__(256, 2)
fused_qkv_det(const __nv_bfloat16* __restrict__ comb,
              const __nv_bfloat16* __restrict__ ipw,
              const float* __restrict__ ipb,
              float* __restrict__ qkv,
              const __nv_bfloat16* __restrict__ w1,
              const float* __restrict__ det_b1,
              const float* __restrict__ det_w2,
              const float* __restrict__ det_b2,
              float* __restrict__ mask)
{
    extern __shared__ char smem[];
    int bx = blockIdx.x;
    if (bx < QKV_BLOCKS) {
        int bn = (bx % 12) * 128;
        int bm = (bx / 12) * 128;
        gemm_body<0,4>(bm, bn, comb + CC, 2*CC, ipw, CC, ipb,
                       qkv, 3*CC, CC, nullptr, nullptr, smem);
    } else {
        int bm = (bx - QKV_BLOCKS) * 64;
        gemm_body<2,2>(bm, 0, comb, 2*CC, w1, 2*CC, det_b1,
                       mask, 1, 2*CC, det_w2, det_b2, smem);
    }
}

// ---- out_proj GEMM (standalone) ---------------------------------------------
__global__ void __launch_bounds__(256, 2)
outproj_gemm(const __nv_bfloat16* __restrict__ ctx,
             const __nv_bfloat16* __restrict__ opw,
             const float* __restrict__ opb,
             float* __restrict__ attnout)
{
    extern __shared__ char smem[];
    gemm_body<0,4>(blockIdx.y * 128, blockIdx.x * 128, ctx, CC, opw, CC,
                   opb, attnout, CC, CC, nullptr, nullptr, smem);
}

// ---- walze (dwconv+BN+GELU) + weight rounding folded into one launch --------
#define WALZE_BLOCKS (BB*CC*HH*WW/256)           // 16384
#define RW_TOTAL (3*CC*CC + CC*CC + 128*2*CC)    // 1,179,648
#define RW_BLOCKS ((RW_TOTAL + 255)/256)         // 4608
__global__ void walze_rw(const float* __restrict__ x,
                         const float* __restrict__ dw_w,
                         const float* __restrict__ dw_b,
                         const float* __restrict__ sh_w,
                         const float* __restrict__ sh_b,
                         const float* __restrict__ mixw,
                         const float* __restrict__ gamma,
                         const float* __restrict__ beta,
                         const float* __restrict__ ipw,
                         const float* __restrict__ opw,
                         const float* __restrict__ w1)
{
    if (blockIdx.x >= WALZE_BLOCKS) {
        int i = (blockIdx.x - WALZE_BLOCKS) * 256 + threadIdx.x;
        const int N1 = 3*CC*CC, N2 = CC*CC, N3 = 128*2*CC;
        if (i < N1)                 g_ipw[i] = __float2bfloat16_rn(ipw[i]);
        else if (i < N1 + N2)       g_opw[i - N1] = __float2bfloat16_rn(opw[i - N1]);
        else if (i < N1 + N2 + N3)  g_w1[i - N1 - N2] = __float2bfloat16_rn(w1[i - N1 - N2]);
        return;
    }
    int idx = blockIdx.x * 256 + threadIdx.x;
    int w = idx & 31;
    int h = (idx >> 5) & 31;
    int c = (idx >> 10) & 511;
    int b = idx >> 19;

    const float* xb = x + ((size_t)(b*CC + c)) * (HH*WW);
    int hm = (h + HH - 1) & 31, hp = (h + 1) & 31;
    int wm = (w + WW - 1) & 31, wp = (w + 1) & 31;

    float v00 = xb[hm*WW+wm], v01 = xb[hm*WW+w], v02 = xb[hm*WW+wp];
    float v10 = xb[h *WW+wm], v11 = xb[h *WW+w], v12 = xb[h *WW+wp];
    float v20 = xb[hp*WW+wm], v21 = xb[hp*WW+w], v22 = xb[hp*WW+wp];

    const float* dk = dw_w + c*9;
    float main_out = v00*dk[0] + v01*dk[1] + v02*dk[2]
                   + v10*dk[3] + v11*dk[4] + v12*dk[5]
                   + v20*dk[6] + v21*dk[7] + v22*dk[8] + dw_b[c];
    float ex = v00*sh_w[0] + v01*sh_w[1] + v02*sh_w[2]
             + v10*sh_w[3] + v11*sh_w[4] + v12*sh_w[5]
             + v20*sh_w[6] + v21*sh_w[7] + v22*sh_w[8] + sh_b[0];

    float mix = 1.0f / (1.0f + __expf(-mixw[0]));
    float combined = mix * main_out + (1.0f - mix) * ex + v11;
    float bn = gamma[c] * combined * rsqrtf(1.0f + 1e-5f) + beta[c];
    g_xwalze[idx] = gelu_exact(bn);
}

// ---------------- pack: transpose x / x_walze into comb rows (bf16) ---------
__global__ void __launch_bounds__(256)
pack_kernel(const float* __restrict__ x)
{
    __shared__ float sx[32][33];
    __shared__ float sw[32][33];
    int bi = blockIdx.x;
    int lt = bi & 31, ct = (bi >> 5) & 15, b = bi >> 9;
    int c0 = ct * 32, l0 = lt * 32;
    int tx = threadIdx.x & 31, ty = threadIdx.x >> 5;
#pragma unroll
    for (int r = ty; r < 32; r += 8) {
        size_t src = (size_t)(b*CC + c0 + r) * LL + l0 + tx;
        sx[r][tx] = x[src];
        sw[r][tx] = g_xwalze[src];
    }
    __syncthreads();
#pragma unroll
    for (int r = ty; r < 32; r += 8) {
        size_t dst = (size_t)(b*LL + l0 + r) * (2*CC) + c0 + tx;
        g_comb[dst]      = __float2bfloat16_rn(sx[tx][r]);
        g_comb[dst + CC] = __float2bfloat16_rn(sw[tx][r]);
    }
}

// ---------------- banded attention: smem-tiled, 2 queries per warp ----------
__global__ void __launch_bounds__(256)
attn_kernel()
{
    __shared__ float ks[96*64];
    __shared__ float vs[96*64];
    int bi = blockIdx.x;
    int qt = bi & 15;
    int h  = (bi >> 4) & 7;
    int b  = bi >> 7;
    int q0 = qt * 64;
    int jlo = max(0, q0 - WHALF);
    int jhi = min(LL - 1, q0 + 63 + WHALF);
    int nrows = jhi - jlo + 1;
    int tid = threadIdx.x;

    const float* kbase = g_qkv + (size_t)(b*LL + jlo) * (3*CC) + CC + h*HD;
    for (int i = tid; i < nrows * 16; i += 256) {
        int r = i >> 4, c = (i & 15) * 4;
        const float* kp = kbase + (size_t)r * (3*CC) + c;
        *(float4*)(ks + r*64 + c) = *(const float4*)kp;
        *(float4*)(vs + r*64 + c) = *(const float4*)(kp + CC);
    }
    __syncthreads();

    int wid = tid >> 5, lane = tid & 31;
    int half = lane >> 4;
    int dl = lane & 15;

#pragma unroll
    for (int pass = 0; pass < 4; pass++) {
        int qe = q0 + wid*8 + pass*2;
        int q  = qe + half;
        const float* qp = g_qkv + (size_t)(b*LL + q) * (3*CC) + h*HD + dl*4;
        float4 qv = *(const float4*)qp;
        qv.x *= 0.125f; qv.y *= 0.125f; qv.z *= 0.125f; qv.w *= 0.125f;

        int wlo = max(0, q - WHALF), whi = min(LL - 1, q + WHALF);
        int plo = max(0, qe - WHALF) - jlo;
        int phi = min(LL - 1, qe + 1 + WHALF) - jlo;

        float lsum = 0.0f;
        float4 acc = make_float4(0.f, 0.f, 0.f, 0.f);
        for (int j = plo; j <= phi; j++) {
            float4 kv = *(const float4*)(ks + j*64 + dl*4);
            float s = qv.x*kv.x + qv.y*kv.y + qv.z*kv.z + qv.w*kv.w;
            s += __shfl_xor_sync(0xffffffffu, s, 8);
            s += __shfl_xor_sync(0xffffffffu, s, 4);
            s += __shfl_xor_sync(0xffffffffu, s, 2);
            s += __shfl_xor_sync(0xffffffffu, s, 1);
            int gj = jlo + j;
            float p = (gj >= wlo && gj <= whi) ? __expf(s) : 0.0f;
            lsum += p;
            float4 vv = *(const float4*)(vs + j*64 + dl*4);
            acc.x += p*vv.x; acc.y += p*vv.y; acc.z += p*vv.z; acc.w += p*vv.w;
        }
        float inv = 1.0f / lsum;
        __nv_bfloat16* op = g_ctx + (size_t)(b*LL + q) * CC + h*HD + dl*4;
        __nv_bfloat162 o01 = __floats2bfloat162_rn(acc.x * inv, acc.y * inv);
        __nv_bfloat162 o23 = __floats2bfloat162_rn(acc.z * inv, acc.w * inv);
        *(uint2*)op = make_uint2(*(uint32_t*)&o01, *(uint32_t*)&o23);
    }
}

// ---------------- gated residual combine: smem-transposed, coalesced --------
__global__ void __launch_bounds__(256)
combine_kernel(float* __restrict__ out)
{
    __shared__ float s[32][33];
    int bi = blockIdx.x;
    int ct = bi & 15, lt = (bi >> 4) & 31, b = bi >> 9;
    int c0 = ct * 32, l0 = lt * 32;
    int tx = threadIdx.x & 31, ty = threadIdx.x >> 5;
#pragma unroll
    for (int r = ty; r < 32; r += 8)
        s[r][tx] = g_attnout[(size_t)(b*LL + l0 + r) * CC + c0 + tx];
    __syncthreads();
    float mk = g_mask[b*LL + l0 + tx];
#pragma unroll
    for (int cr = ty; cr < 32; cr += 8) {
        size_t o = (size_t)(b*CC + c0 + cr) * LL + l0 + tx;
        out[o] = g_xwalze[o] + mk * s[tx][cr];
    }
}

// ---------------- host launcher ---------------------------------------------
extern "C" void kernel_launch(void* const* d_in, const int* in_sizes, int n_in,
                              void* d_out, int out_size)
{
    const float* x      = (const float*)d_in[0];
    const float* dw_w   = (const float*)d_in[1];
    const float* dw_b   = (const float*)d_in[2];
    const float* sh_w   = (const float*)d_in[3];
    const float* sh_b   = (const float*)d_in[4];
    const float* mixw   = (const float*)d_in[5];
    const float* gamma  = (const float*)d_in[6];
    const float* beta   = (const float*)d_in[7];
    const float* det_w1 = (const float*)d_in[8];
    const float* det_b1 = (const float*)d_in[9];
    const float* det_w2 = (const float*)d_in[10];
    const float* det_b2 = (const float*)d_in[11];
    const float* ipw    = (const float*)d_in[12];
    const float* ipb    = (const float*)d_in[13];
    const float* opw    = (const float*)d_in[14];
    const float* opb    = (const float*)d_in[15];
    float* out = (float*)d_out;

    __nv_bfloat16 *p_comb, *p_ctx, *p_ipw, *p_opw, *p_w1;
    float *p_qkv, *p_mask, *p_attnout;
    cudaGetSymbolAddress((void**)&p_comb,    g_comb);
    cudaGetSymbolAddress((void**)&p_qkv,     g_qkv);
    cudaGetSymbolAddress((void**)&p_ctx,     g_ctx);
    cudaGetSymbolAddress((void**)&p_ipw,     g_ipw);
    cudaGetSymbolAddress((void**)&p_opw,     g_opw);
    cudaGetSymbolAddress((void**)&p_w1,      g_w1);
    cudaGetSymbolAddress((void**)&p_mask,    g_mask);
    cudaGetSymbolAddress((void**)&p_attnout, g_attnout);

    const int SMEM128 = 3 * (128*128 + 16384);   // 98304
    cudaFuncSetAttribute((const void*)fused_qkv_det,
                         cudaFuncAttributeMaxDynamicSharedMemorySize, SMEM128);
    cudaFuncSetAttribute((const void*)outproj_gemm,
                         cudaFuncAttributeMaxDynamicSharedMemorySize, SMEM128);

    // 1) walze (dwconv+BN+GELU) + bf16 weight rounding, one launch
    walze_rw<<<WALZE_BLOCKS + RW_BLOCKS, 256>>>(
        x, dw_w, dw_b, sh_w, sh_b, mixw, gamma, beta, ipw, opw, det_w1);

    // 2) pack: transpose into comb rows (bf16), fully coalesced
    pack_kernel<<<BB*16*32, 256>>>(x);

    // 3) fused QKV GEMM + detector GEMM/head (one grid, det fills QKV's tail)
    fused_qkv_det<<<QKV_BLOCKS + 128, 256, SMEM128>>>(
        p_comb, p_ipw, ipb, p_qkv, p_w1, det_b1, det_w2, det_b2, p_mask);

    // 4) banded attention (smem-tiled)
    attn_kernel<<<BB*NHD*(LL/64), 256>>>();

    // 5) out_proj GEMM
    {
        dim3 g(CC/128, (BB*LL)/128);
        outproj_gemm<<<g, 256, SMEM128>>>(p_ctx, p_opw, opb, p_attnout);
    }

    // 6) gated residual combine (transposed, coalesced)
    combine_kernel<<<BB*16*32, 256>>>(out);
}